// round 5
// baseline (speedup 1.0000x reference)
#include <cuda_runtime.h>

// Problem constants
#define BB 2048
#define SS 512
#define DD 128
#define HH 64
#define H4 16
#define OO 8

// Scratch (device globals — no runtime allocation allowed)
__device__ float g_z1[BB * H4];
__device__ float g_mu1[HH], g_rs1[HH];
__device__ float g_mu2[H4], g_rs2[H4];

// ---------------------------------------------------------------------------
// k1: fused input projection + ReLU RNN recurrence.
// Grid 128 CTAs x 128 threads. CTA owns 16 batch rows; each warp owns 4 rows
// (warp-private, so only __syncwarp in the mainloop). Lane owns j = {lane,
// lane+32}. Weights live in SMEM in d-major float4 layout (conflict-free
// LDS.128), x rows staged per-step into SMEM and read as float4 broadcasts.
// ---------------------------------------------------------------------------
#define K1_WARPS 4
#define K1_RPW 4                       // rows per warp
#define K1_ROWS (K1_WARPS * K1_RPW)    // 16 rows per CTA
#define K1_THREADS (K1_WARPS * 32)
#define K1_GRID (BB / K1_ROWS)         // 128
// smem: wih 32KB + whh 16KB + x stage 8KB + h 4KB = 60KB
#define K1_SMEM (2048 * 16 + 1024 * 16 + K1_ROWS * DD * 4 + K1_ROWS * HH * 4)

__global__ void __launch_bounds__(K1_THREADS, 1)
rnn_fused_kernel(const float* __restrict__ x, const float* __restrict__ h0,
                 const float* __restrict__ Wih, const float* __restrict__ Whh,
                 const float* __restrict__ bih, const float* __restrict__ bhh,
                 float* __restrict__ hT_out) {
    extern __shared__ float smem[];
    float4* s_wih = (float4*)smem;                 // [32 dq][64 j]
    float4* s_whh = s_wih + 2048;                  // [16 kq][64 j]
    float*  s_x   = (float*)(s_whh + 1024);        // [16 r][128 d]
    float*  s_h   = s_x + K1_ROWS * DD;            // [16 r][64 j]

    const int tid  = threadIdx.x;
    const int warp = tid >> 5;
    const int lane = tid & 31;

    // Stage W_ih ([64][128] row-major) as d-major quads: s_wih[dq*64 + j]
    for (int idx = tid; idx < 2048; idx += K1_THREADS) {
        int dq = idx >> 6, j = idx & 63;
        s_wih[idx] = *(const float4*)(Wih + j * DD + dq * 4);
    }
    // Stage W_hh ([64][64]) as k-major quads: s_whh[kq*64 + j]
    for (int idx = tid; idx < 1024; idx += K1_THREADS) {
        int kq = idx >> 6, j = idx & 63;
        s_whh[idx] = *(const float4*)(Whh + j * HH + kq * 4);
    }

    const int rB = warp * K1_RPW;                  // CTA-local first row
    const int b0 = blockIdx.x * K1_ROWS + rB;      // global first row

    // init h from h0 [1,B,H]
#pragma unroll
    for (int r = 0; r < K1_RPW; r++) {
        s_h[(rB + r) * HH + lane]      = h0[(b0 + r) * HH + lane];
        s_h[(rB + r) * HH + lane + 32] = h0[(b0 + r) * HH + lane + 32];
    }
    const float bj0 = bih[lane] + bhh[lane];
    const float bj1 = bih[lane + 32] + bhh[lane + 32];
    __syncthreads();

    // per-row x pointers (lane covers d = 4*lane .. 4*lane+3)
    const float* xp[K1_RPW];
#pragma unroll
    for (int r = 0; r < K1_RPW; r++)
        xp[r] = x + (size_t)(b0 + r) * SS * DD + lane * 4;

    // prefetch t = 0
    float4 xr[K1_RPW];
#pragma unroll
    for (int r = 0; r < K1_RPW; r++) xr[r] = *(const float4*)(xp[r]);

    for (int t = 0; t < SS; t++) {
        // stage current x tile (warp-private rows)
#pragma unroll
        for (int r = 0; r < K1_RPW; r++)
            *(float4*)(s_x + (rB + r) * DD + lane * 4) = xr[r];
        __syncwarp();

        // prefetch next timestep (latency overlapped with compute)
        if (t + 1 < SS) {
#pragma unroll
            for (int r = 0; r < K1_RPW; r++)
                xr[r] = *(const float4*)(xp[r] + (size_t)(t + 1) * DD);
        }

        float acc0[K1_RPW], acc1[K1_RPW];
#pragma unroll
        for (int r = 0; r < K1_RPW; r++) { acc0[r] = bj0; acc1[r] = bj1; }

        // input projection: acc[j] += sum_d x[r][d] * Wih[j][d]
#pragma unroll 8
        for (int dq = 0; dq < 32; dq++) {
            float4 w0 = s_wih[dq * 64 + lane];
            float4 w1 = s_wih[dq * 64 + lane + 32];
#pragma unroll
            for (int r = 0; r < K1_RPW; r++) {
                float4 xv = *(const float4*)(s_x + (rB + r) * DD + dq * 4);
                acc0[r] = fmaf(xv.x, w0.x, acc0[r]);
                acc0[r] = fmaf(xv.y, w0.y, acc0[r]);
                acc0[r] = fmaf(xv.z, w0.z, acc0[r]);
                acc0[r] = fmaf(xv.w, w0.w, acc0[r]);
                acc1[r] = fmaf(xv.x, w1.x, acc1[r]);
                acc1[r] = fmaf(xv.y, w1.y, acc1[r]);
                acc1[r] = fmaf(xv.z, w1.z, acc1[r]);
                acc1[r] = fmaf(xv.w, w1.w, acc1[r]);
            }
        }
        // recurrence: acc[j] += sum_k h[r][k] * Whh[j][k]
#pragma unroll 4
        for (int kq = 0; kq < 16; kq++) {
            float4 w0 = s_whh[kq * 64 + lane];
            float4 w1 = s_whh[kq * 64 + lane + 32];
#pragma unroll
            for (int r = 0; r < K1_RPW; r++) {
                float4 hv = *(const float4*)(s_h + (rB + r) * HH + kq * 4);
                acc0[r] = fmaf(hv.x, w0.x, acc0[r]);
                acc0[r] = fmaf(hv.y, w0.y, acc0[r]);
                acc0[r] = fmaf(hv.z, w0.z, acc0[r]);
                acc0[r] = fmaf(hv.w, w0.w, acc0[r]);
                acc1[r] = fmaf(hv.x, w1.x, acc1[r]);
                acc1[r] = fmaf(hv.y, w1.y, acc1[r]);
                acc1[r] = fmaf(hv.z, w1.z, acc1[r]);
                acc1[r] = fmaf(hv.w, w1.w, acc1[r]);
            }
        }
        __syncwarp();  // all lanes done reading s_h/s_x
#pragma unroll
        for (int r = 0; r < K1_RPW; r++) {
            s_h[(rB + r) * HH + lane]      = fmaxf(acc0[r], 0.0f);
            s_h[(rB + r) * HH + lane + 32] = fmaxf(acc1[r], 0.0f);
        }
        __syncwarp();  // h visible before next iteration reads it
    }

    // write hT (this region of d_out is the hidden-state output)
#pragma unroll
    for (int r = 0; r < K1_RPW; r++) {
        hT_out[(b0 + r) * HH + lane]      = s_h[(rB + r) * HH + lane];
        hT_out[(b0 + r) * HH + lane + 32] = s_h[(rB + r) * HH + lane + 32];
    }
}

// ---------------------------------------------------------------------------
// k2: BatchNorm1d stats over hT (two-pass, deterministic tree reduce).
// One CTA per feature (64 CTAs x 256 threads).
// ---------------------------------------------------------------------------
__global__ void bn1_stats_kernel(const float* __restrict__ hT) {
    const int f = blockIdx.x, tid = threadIdx.x;
    __shared__ float red[256];
    __shared__ float s_mu;

    float s = 0.0f;
    for (int b = tid; b < BB; b += 256) s += hT[b * HH + f];
    red[tid] = s;
    __syncthreads();
    for (int w = 128; w > 0; w >>= 1) {
        if (tid < w) red[tid] += red[tid + w];
        __syncthreads();
    }
    if (tid == 0) s_mu = red[0] * (1.0f / BB);
    __syncthreads();
    const float mu = s_mu;

    float s2 = 0.0f;
    for (int b = tid; b < BB; b += 256) {
        float v = hT[b * HH + f] - mu;
        s2 += v * v;
    }
    red[tid] = s2;
    __syncthreads();
    for (int w = 128; w > 0; w >>= 1) {
        if (tid < w) red[tid] += red[tid + w];
        __syncthreads();
    }
    if (tid == 0) {
        g_mu1[f] = mu;
        g_rs1[f] = rsqrtf(red[0] * (1.0f / BB) + 1e-5f);
    }
}

// ---------------------------------------------------------------------------
// k3: z1 = relu(BN1(hT) @ fc1_W^T + fc1_b). Thread per batch row.
// ---------------------------------------------------------------------------
__global__ void fc1_kernel(const float* __restrict__ hT,
                           const float* __restrict__ g1, const float* __restrict__ be1,
                           const float* __restrict__ fW, const float* __restrict__ fb) {
    __shared__ float sW[H4 * HH];
    __shared__ float sc[HH], sh[HH], sb[H4];
    const int tid = threadIdx.x;
    for (int i = tid; i < H4 * HH; i += 256) sW[i] = fW[i];
    if (tid < HH) {
        float s = g_rs1[tid] * g1[tid];
        sc[tid] = s;
        sh[tid] = be1[tid] - g_mu1[tid] * s;
    }
    if (tid < H4) sb[tid] = fb[tid];
    __syncthreads();

    const int b = blockIdx.x * 256 + tid;
    float acc[H4];
#pragma unroll
    for (int o = 0; o < H4; o++) acc[o] = sb[o];
#pragma unroll 8
    for (int j = 0; j < HH; j++) {
        float v = fmaf(hT[b * HH + j], sc[j], sh[j]);
#pragma unroll
        for (int o = 0; o < H4; o++) acc[o] = fmaf(v, sW[o * HH + j], acc[o]);
    }
#pragma unroll
    for (int o = 0; o < H4; o++) g_z1[b * H4 + o] = fmaxf(acc[o], 0.0f);
}

// ---------------------------------------------------------------------------
// k4: BatchNorm stats over z1 (16 features). One warp per feature.
// ---------------------------------------------------------------------------
__global__ void bn2_stats_kernel() {
    const int o = threadIdx.x >> 5, lane = threadIdx.x & 31;
    float s = 0.0f;
    for (int b = lane; b < BB; b += 32) s += g_z1[b * H4 + o];
#pragma unroll
    for (int d = 16; d > 0; d >>= 1) s += __shfl_xor_sync(0xFFFFFFFFu, s, d);
    const float mu = s * (1.0f / BB);

    float s2 = 0.0f;
    for (int b = lane; b < BB; b += 32) {
        float v = g_z1[b * H4 + o] - mu;
        s2 += v * v;
    }
#pragma unroll
    for (int d = 16; d > 0; d >>= 1) s2 += __shfl_xor_sync(0xFFFFFFFFu, s2, d);
    if (lane == 0) {
        g_mu2[o] = mu;
        g_rs2[o] = rsqrtf(s2 * (1.0f / BB) + 1e-5f);
    }
}

// ---------------------------------------------------------------------------
// k5: out = BN2(z1) @ fc2_W^T + fc2_b. Thread per batch row.
// ---------------------------------------------------------------------------
__global__ void fc2_kernel(const float* __restrict__ g2, const float* __restrict__ be2,
                           const float* __restrict__ fW, const float* __restrict__ fb,
                           float* __restrict__ out) {
    __shared__ float sW[OO * H4];
    __shared__ float sc[H4], sh[H4], sb[OO];
    const int tid = threadIdx.x;
    if (tid < OO * H4) sW[tid] = fW[tid];
    if (tid < H4) {
        float s = g_rs2[tid] * g2[tid];
        sc[tid] = s;
        sh[tid] = be2[tid] - g_mu2[tid] * s;
    }
    if (tid < OO) sb[tid] = fb[tid];
    __syncthreads();

    const int b = blockIdx.x * 256 + tid;
    float z[H4];
#pragma unroll
    for (int o = 0; o < H4; o++) z[o] = fmaf(g_z1[b * H4 + o], sc[o], sh[o]);
#pragma unroll
    for (int c = 0; c < OO; c++) {
        float a = sb[c];
#pragma unroll
        for (int o = 0; o < H4; o++) a = fmaf(z[o], sW[c * H4 + o], a);
        out[b * OO + c] = a;
    }
}

// ---------------------------------------------------------------------------
// Launch. Output layout (reference returns (out, hT[None])):
//   d_out[0 .. B*O)                : out  [2048, 8]
//   d_out[B*O .. B*O + B*H)        : hT   [1, 2048, 64]
// ---------------------------------------------------------------------------
extern "C" void kernel_launch(void* const* d_in, const int* in_sizes, int n_in,
                              void* d_out, int out_size) {
    const float* x    = (const float*)d_in[0];
    const float* h0   = (const float*)d_in[1];
    const float* Wih  = (const float*)d_in[2];
    const float* Whh  = (const float*)d_in[3];
    const float* bih  = (const float*)d_in[4];
    const float* bhh  = (const float*)d_in[5];
    const float* bn1g = (const float*)d_in[6];
    const float* bn1b = (const float*)d_in[7];
    const float* fc1W = (const float*)d_in[8];
    const float* fc1b = (const float*)d_in[9];
    const float* bn2g = (const float*)d_in[10];
    const float* bn2b = (const float*)d_in[11];
    const float* fc2W = (const float*)d_in[12];
    const float* fc2b = (const float*)d_in[13];

    float* out = (float*)d_out;
    float* hT  = out + BB * OO;

    cudaFuncSetAttribute(rnn_fused_kernel,
                         cudaFuncAttributeMaxDynamicSharedMemorySize, K1_SMEM);

    rnn_fused_kernel<<<K1_GRID, K1_THREADS, K1_SMEM>>>(x, h0, Wih, Whh, bih, bhh, hT);
    bn1_stats_kernel<<<HH, 256>>>(hT);
    fc1_kernel<<<BB / 256, 256>>>(hT, bn1g, bn1b, fc1W, fc1b);
    bn2_stats_kernel<<<1, 512>>>();
    fc2_kernel<<<BB / 256, 256>>>(bn2g, bn2b, fc2W, fc2b, out);
}